// round 16
// baseline (speedup 1.0000x reference)
#include <cuda_runtime.h>

// ---------------- global accumulators (allocation-free scratch) -------------
__device__ double g_inter = 0.0;
__device__ double g_desire_sum = 0.0;
__device__ unsigned long long g_count = 0ull;
__device__ unsigned int g_ticket = 0u;

// Key idea: dist^2 is a sum of squares -> partial sums are monotone.
// If the first-32-column partial already exceeds margin^2, the row is
// classified with certainty. Only rows whose partial is <= margin^2 need the
// remaining 96 columns (rare-to-never for this data; handled exactly by a
// fallback path, so the kernel is correct for ANY input).
// Traffic: 68 MB instead of 269 MB. Each row's first 128B is one full,
// aligned 128B line -> every fetched line is 100% used.

#define MARGIN_SQ 0.390625f   // (1.25/2)^2

// Load the first-128B slice of a 16-row tile: group g (8 lanes) owns rows
// tile*16+g*4 .. +3; lane j loads float4 slot j (j<8 -> cols 0..31).
#define LOAD16(T, A, B)                                                   \
    do {                                                                  \
        if ((T) < n_t16) {                                                \
            const int _r = (T) * 16 + g * 4;                              \
            const int _b = _r * 32 + j;                                   \
            A[0] = o1[_b];      B[0] = o2[_b];                            \
            A[1] = o1[_b + 32]; B[1] = o2[_b + 32];                       \
            A[2] = o1[_b + 64]; B[2] = o2[_b + 64];                       \
            A[3] = o1[_b + 96]; B[3] = o2[_b + 96];                       \
        }                                                                 \
    } while (0)

__global__ __launch_bounds__(256, 2)
void fra_partial_kernel(const float4* __restrict__ o1,
                        const float4* __restrict__ o2,
                        const float4* __restrict__ des4,
                        const float*  __restrict__ des,
                        float* __restrict__ out,
                        int n_rows) {
    const int lane = threadIdx.x & 31;
    const int wib  = threadIdx.x >> 5;
    const int wpb  = blockDim.x >> 5;
    const int wg   = blockIdx.x * wpb + wib;
    const int tw   = gridDim.x * wpb;

    const int g = lane >> 3;   // 8-lane group: rows tile*16+g*4 .. +3
    const int j = lane & 7;    // float4 slot 0..7 (columns 4j..4j+3)

    double       l_inter = 0.0, l_des = 0.0;
    unsigned int l_cnt = 0u;

    const int n_t16 = n_rows >> 4;   // 16-row tiles

    float4 aA[4], bA[4], aB[4], bB[4];

    int t = wg;
    LOAD16(t, aA, bA);

    while (t < n_t16) {
        // ---- stage A compute, prefetch into B first ----
        int nx = t + tw;
        LOAD16(nx, aB, bB);
        {
            float s[4];
            #pragma unroll
            for (int k = 0; k < 4; k++) {
                float dx = aA[k].x - bA[k].x; float acc = dx * dx;
                dx = aA[k].y - bA[k].y; acc += dx * dx;
                dx = aA[k].z - bA[k].z; acc += dx * dx;
                dx = aA[k].w - bA[k].w; acc += dx * dx;
                s[k] = acc;
            }
            #pragma unroll
            for (int off = 4; off > 0; off >>= 1)
                #pragma unroll
                for (int k = 0; k < 4; k++)
                    s[k] += __shfl_xor_sync(0xffffffffu, s[k], off);

            // Rare exact fallback: any row whose 32-col partial is under
            // the threshold gets the remaining 96 columns.
            const bool need = (s[0] <= MARGIN_SQ) | (s[1] <= MARGIN_SQ) |
                              (s[2] <= MARGIN_SQ) | (s[3] <= MARGIN_SQ);
            if (__ballot_sync(0xffffffffu, need)) {
                const int r = t * 16 + g * 4;
                #pragma unroll
                for (int k = 0; k < 4; k++) {
                    float e = 0.0f;
                    #pragma unroll
                    for (int m = 1; m < 4; m++) {
                        const float4 a = o1[(r + k) * 32 + j + 8 * m];
                        const float4 b = o2[(r + k) * 32 + j + 8 * m];
                        float dx = a.x - b.x; e += dx * dx;
                        dx = a.y - b.y; e += dx * dx;
                        dx = a.z - b.z; e += dx * dx;
                        dx = a.w - b.w; e += dx * dx;
                    }
                    #pragma unroll
                    for (int off = 4; off > 0; off >>= 1)
                        e += __shfl_xor_sync(0xffffffffu, e, off);
                    s[k] += e;
                }
            }

            if (j == 0) {
                const float4 dv = des4[t * 4 + g];
                const float dk[4] = {dv.x, dv.y, dv.z, dv.w};
                #pragma unroll
                for (int k = 0; k < 4; k++) {
                    l_des += (double)dk[k];
                    if (s[k] > MARGIN_SQ) { l_cnt += 1u; l_inter += (double)dk[k]; }
                }
            }
        }
        t = nx;
        if (t >= n_t16) break;

        // ---- stage B compute, prefetch into A first ----
        nx = t + tw;
        LOAD16(nx, aA, bA);
        {
            float s[4];
            #pragma unroll
            for (int k = 0; k < 4; k++) {
                float dx = aB[k].x - bB[k].x; float acc = dx * dx;
                dx = aB[k].y - bB[k].y; acc += dx * dx;
                dx = aB[k].z - bB[k].z; acc += dx * dx;
                dx = aB[k].w - bB[k].w; acc += dx * dx;
                s[k] = acc;
            }
            #pragma unroll
            for (int off = 4; off > 0; off >>= 1)
                #pragma unroll
                for (int k = 0; k < 4; k++)
                    s[k] += __shfl_xor_sync(0xffffffffu, s[k], off);

            const bool need = (s[0] <= MARGIN_SQ) | (s[1] <= MARGIN_SQ) |
                              (s[2] <= MARGIN_SQ) | (s[3] <= MARGIN_SQ);
            if (__ballot_sync(0xffffffffu, need)) {
                const int r = t * 16 + g * 4;
                #pragma unroll
                for (int k = 0; k < 4; k++) {
                    float e = 0.0f;
                    #pragma unroll
                    for (int m = 1; m < 4; m++) {
                        const float4 a = o1[(r + k) * 32 + j + 8 * m];
                        const float4 b = o2[(r + k) * 32 + j + 8 * m];
                        float dx = a.x - b.x; e += dx * dx;
                        dx = a.y - b.y; e += dx * dx;
                        dx = a.z - b.z; e += dx * dx;
                        dx = a.w - b.w; e += dx * dx;
                    }
                    #pragma unroll
                    for (int off = 4; off > 0; off >>= 1)
                        e += __shfl_xor_sync(0xffffffffu, e, off);
                    s[k] += e;
                }
            }

            if (j == 0) {
                const float4 dv = des4[t * 4 + g];
                const float dk[4] = {dv.x, dv.y, dv.z, dv.w};
                #pragma unroll
                for (int k = 0; k < 4; k++) {
                    l_des += (double)dk[k];
                    if (s[k] > MARGIN_SQ) { l_cnt += 1u; l_inter += (double)dk[k]; }
                }
            }
        }
        t = nx;
    }

    // Tail rows (n_rows % 16): warp 0, full 128-column exact compute.
    if (wg == 0) {
        for (int row = n_t16 * 16; row < n_rows; row++) {
            float s = 0.0f;
            if (g == 0) {
                const int base = row * 32 + j;
                #pragma unroll
                for (int m = 0; m < 4; m++) {
                    const float4 a = o1[base + 8 * m];
                    const float4 b = o2[base + 8 * m];
                    float dx = a.x - b.x; s += dx * dx;
                    dx = a.y - b.y; s += dx * dx;
                    dx = a.z - b.z; s += dx * dx;
                    dx = a.w - b.w; s += dx * dx;
                }
            }
            #pragma unroll
            for (int off = 4; off > 0; off >>= 1)
                s += __shfl_xor_sync(0xffffffffu, s, off);
            if (lane == 0) {
                const float dsr = des[row];
                l_des += (double)dsr;
                if (s > MARGIN_SQ) { l_cnt += 1u; l_inter += (double)dsr; }
            }
        }
    }

    // Warp reduction (accumulators live on j==0 lanes; reduce all 32).
    #pragma unroll
    for (int off = 16; off > 0; off >>= 1) {
        l_inter += __shfl_xor_sync(0xffffffffu, l_inter, off);
        l_des   += __shfl_xor_sync(0xffffffffu, l_des,   off);
        l_cnt   += __shfl_xor_sync(0xffffffffu, l_cnt,   off);
    }

    __shared__ double       s_i[8], s_d[8];
    __shared__ unsigned int s_c[8];
    __shared__ bool         s_last;
    if (lane == 0) { s_i[wib] = l_inter; s_d[wib] = l_des; s_c[wib] = l_cnt; }
    __syncthreads();

    if (threadIdx.x == 0) {
        double       bi = 0.0, bd = 0.0;
        unsigned int bc = 0u;
        for (int w = 0; w < wpb; w++) { bi += s_i[w]; bd += s_d[w]; bc += s_c[w]; }
        atomicAdd(&g_inter, bi);
        atomicAdd(&g_desire_sum, bd);
        atomicAdd(&g_count, (unsigned long long)bc);
        __threadfence();
        s_last = (atomicAdd(&g_ticket, 1u) == gridDim.x - 1);
    }
    __syncthreads();

    if (s_last && threadIdx.x == 0) {
        __threadfence();
        const double inter = atomicAdd(&g_inter, 0.0);
        const double dsum  = atomicAdd(&g_desire_sum, 0.0);
        const double cnt   = (double)atomicAdd(&g_count, 0ull);
        const double uni   = cnt + dsum - inter;
        out[0] = (float)((inter + 1e-6) / (uni + 1e-6));
        g_inter = 0.0;
        g_desire_sum = 0.0;
        g_count = 0ull;
        __threadfence();
        g_ticket = 0u;
    }
}

extern "C" void kernel_launch(void* const* d_in, const int* in_sizes, int n_in,
                              void* d_out, int out_size) {
    const float4* o1   = (const float4*)d_in[0];
    const float4* o2   = (const float4*)d_in[1];
    const float*  des  = (const float*)d_in[2];
    float*        out  = (float*)d_out;

    const int n_rows = in_sizes[2];   // N = 262144

    // Proven R8 shape: 296 = 148 SMs x 2 blocks, 256 threads, one wave.
    fra_partial_kernel<<<296, 256>>>(o1, o2, (const float4*)des, des, out, n_rows);
}

// round 17
// speedup vs baseline: 1.0514x; 1.0514x over previous
#include <cuda_runtime.h>

// ---------------- global accumulators (allocation-free scratch) -------------
__device__ double g_inter = 0.0;
__device__ double g_desire_sum = 0.0;
__device__ unsigned long long g_count = 0ull;
__device__ unsigned int g_ticket = 0u;

// Key idea: dist^2 is a sum of squares -> partial sums are monotone.
// If the first-32-column partial already exceeds margin^2, the row is
// classified with certainty. Only rows whose partial is <= margin^2 need the
// remaining 96 columns (rare-to-never for this data; handled exactly by a
// fallback path, so the kernel is correct for ANY input).
// Traffic: 68 MB instead of 269 MB. Each row's first 128B is one full,
// aligned 128B line -> every fetched line is 100% used.

#define MARGIN_SQ 0.390625f   // (1.25/2)^2

// Load the first-128B slice of a 16-row tile: group g (8 lanes) owns rows
// tile*16+g*4 .. +3; lane j loads float4 slot j (j<8 -> cols 0..31).
#define LOAD16(T, A, B)                                                   \
    do {                                                                  \
        if ((T) < n_t16) {                                                \
            const int _r = (T) * 16 + g * 4;                              \
            const int _b = _r * 32 + j;                                   \
            A[0] = o1[_b];      B[0] = o2[_b];                            \
            A[1] = o1[_b + 32]; B[1] = o2[_b + 32];                       \
            A[2] = o1[_b + 64]; B[2] = o2[_b + 64];                       \
            A[3] = o1[_b + 96]; B[3] = o2[_b + 96];                       \
        }                                                                 \
    } while (0)

__global__ __launch_bounds__(256, 2)
void fra_partial_kernel(const float4* __restrict__ o1,
                        const float4* __restrict__ o2,
                        const float4* __restrict__ des4,
                        const float*  __restrict__ des,
                        float* __restrict__ out,
                        int n_rows) {
    const int lane = threadIdx.x & 31;
    const int wib  = threadIdx.x >> 5;
    const int wpb  = blockDim.x >> 5;
    const int wg   = blockIdx.x * wpb + wib;
    const int tw   = gridDim.x * wpb;

    const int g = lane >> 3;   // 8-lane group: rows tile*16+g*4 .. +3
    const int j = lane & 7;    // float4 slot 0..7 (columns 4j..4j+3)

    double       l_inter = 0.0, l_des = 0.0;
    unsigned int l_cnt = 0u;

    const int n_t16 = n_rows >> 4;   // 16-row tiles

    float4 aA[4], bA[4], aB[4], bB[4];

    int t = wg;
    LOAD16(t, aA, bA);

    while (t < n_t16) {
        // ---- stage A compute, prefetch into B first ----
        int nx = t + tw;
        LOAD16(nx, aB, bB);
        {
            float s[4];
            #pragma unroll
            for (int k = 0; k < 4; k++) {
                float dx = aA[k].x - bA[k].x; float acc = dx * dx;
                dx = aA[k].y - bA[k].y; acc += dx * dx;
                dx = aA[k].z - bA[k].z; acc += dx * dx;
                dx = aA[k].w - bA[k].w; acc += dx * dx;
                s[k] = acc;
            }
            #pragma unroll
            for (int off = 4; off > 0; off >>= 1)
                #pragma unroll
                for (int k = 0; k < 4; k++)
                    s[k] += __shfl_xor_sync(0xffffffffu, s[k], off);

            // Rare exact fallback: any row whose 32-col partial is under
            // the threshold gets the remaining 96 columns.
            const bool need = (s[0] <= MARGIN_SQ) | (s[1] <= MARGIN_SQ) |
                              (s[2] <= MARGIN_SQ) | (s[3] <= MARGIN_SQ);
            if (__ballot_sync(0xffffffffu, need)) {
                const int r = t * 16 + g * 4;
                #pragma unroll
                for (int k = 0; k < 4; k++) {
                    float e = 0.0f;
                    #pragma unroll
                    for (int m = 1; m < 4; m++) {
                        const float4 a = o1[(r + k) * 32 + j + 8 * m];
                        const float4 b = o2[(r + k) * 32 + j + 8 * m];
                        float dx = a.x - b.x; e += dx * dx;
                        dx = a.y - b.y; e += dx * dx;
                        dx = a.z - b.z; e += dx * dx;
                        dx = a.w - b.w; e += dx * dx;
                    }
                    #pragma unroll
                    for (int off = 4; off > 0; off >>= 1)
                        e += __shfl_xor_sync(0xffffffffu, e, off);
                    s[k] += e;
                }
            }

            if (j == 0) {
                const float4 dv = des4[t * 4 + g];
                const float dk[4] = {dv.x, dv.y, dv.z, dv.w};
                #pragma unroll
                for (int k = 0; k < 4; k++) {
                    l_des += (double)dk[k];
                    if (s[k] > MARGIN_SQ) { l_cnt += 1u; l_inter += (double)dk[k]; }
                }
            }
        }
        t = nx;
        if (t >= n_t16) break;

        // ---- stage B compute, prefetch into A first ----
        nx = t + tw;
        LOAD16(nx, aA, bA);
        {
            float s[4];
            #pragma unroll
            for (int k = 0; k < 4; k++) {
                float dx = aB[k].x - bB[k].x; float acc = dx * dx;
                dx = aB[k].y - bB[k].y; acc += dx * dx;
                dx = aB[k].z - bB[k].z; acc += dx * dx;
                dx = aB[k].w - bB[k].w; acc += dx * dx;
                s[k] = acc;
            }
            #pragma unroll
            for (int off = 4; off > 0; off >>= 1)
                #pragma unroll
                for (int k = 0; k < 4; k++)
                    s[k] += __shfl_xor_sync(0xffffffffu, s[k], off);

            const bool need = (s[0] <= MARGIN_SQ) | (s[1] <= MARGIN_SQ) |
                              (s[2] <= MARGIN_SQ) | (s[3] <= MARGIN_SQ);
            if (__ballot_sync(0xffffffffu, need)) {
                const int r = t * 16 + g * 4;
                #pragma unroll
                for (int k = 0; k < 4; k++) {
                    float e = 0.0f;
                    #pragma unroll
                    for (int m = 1; m < 4; m++) {
                        const float4 a = o1[(r + k) * 32 + j + 8 * m];
                        const float4 b = o2[(r + k) * 32 + j + 8 * m];
                        float dx = a.x - b.x; e += dx * dx;
                        dx = a.y - b.y; e += dx * dx;
                        dx = a.z - b.z; e += dx * dx;
                        dx = a.w - b.w; e += dx * dx;
                    }
                    #pragma unroll
                    for (int off = 4; off > 0; off >>= 1)
                        e += __shfl_xor_sync(0xffffffffu, e, off);
                    s[k] += e;
                }
            }

            if (j == 0) {
                const float4 dv = des4[t * 4 + g];
                const float dk[4] = {dv.x, dv.y, dv.z, dv.w};
                #pragma unroll
                for (int k = 0; k < 4; k++) {
                    l_des += (double)dk[k];
                    if (s[k] > MARGIN_SQ) { l_cnt += 1u; l_inter += (double)dk[k]; }
                }
            }
        }
        t = nx;
    }

    // Tail rows (n_rows % 16): warp 0, full 128-column exact compute.
    if (wg == 0) {
        for (int row = n_t16 * 16; row < n_rows; row++) {
            float s = 0.0f;
            if (g == 0) {
                const int base = row * 32 + j;
                #pragma unroll
                for (int m = 0; m < 4; m++) {
                    const float4 a = o1[base + 8 * m];
                    const float4 b = o2[base + 8 * m];
                    float dx = a.x - b.x; s += dx * dx;
                    dx = a.y - b.y; s += dx * dx;
                    dx = a.z - b.z; s += dx * dx;
                    dx = a.w - b.w; s += dx * dx;
                }
            }
            #pragma unroll
            for (int off = 4; off > 0; off >>= 1)
                s += __shfl_xor_sync(0xffffffffu, s, off);
            if (lane == 0) {
                const float dsr = des[row];
                l_des += (double)dsr;
                if (s > MARGIN_SQ) { l_cnt += 1u; l_inter += (double)dsr; }
            }
        }
    }

    // Warp reduction (accumulators live on j==0 lanes; reduce all 32).
    #pragma unroll
    for (int off = 16; off > 0; off >>= 1) {
        l_inter += __shfl_xor_sync(0xffffffffu, l_inter, off);
        l_des   += __shfl_xor_sync(0xffffffffu, l_des,   off);
        l_cnt   += __shfl_xor_sync(0xffffffffu, l_cnt,   off);
    }

    __shared__ double       s_i[8], s_d[8];
    __shared__ unsigned int s_c[8];
    __shared__ bool         s_last;
    if (lane == 0) { s_i[wib] = l_inter; s_d[wib] = l_des; s_c[wib] = l_cnt; }
    __syncthreads();

    if (threadIdx.x == 0) {
        double       bi = 0.0, bd = 0.0;
        unsigned int bc = 0u;
        for (int w = 0; w < wpb; w++) { bi += s_i[w]; bd += s_d[w]; bc += s_c[w]; }
        atomicAdd(&g_inter, bi);
        atomicAdd(&g_desire_sum, bd);
        atomicAdd(&g_count, (unsigned long long)bc);
        __threadfence();
        s_last = (atomicAdd(&g_ticket, 1u) == gridDim.x - 1);
    }
    __syncthreads();

    if (s_last && threadIdx.x == 0) {
        __threadfence();
        const double inter = atomicAdd(&g_inter, 0.0);
        const double dsum  = atomicAdd(&g_desire_sum, 0.0);
        const double cnt   = (double)atomicAdd(&g_count, 0ull);
        const double uni   = cnt + dsum - inter;
        out[0] = (float)((inter + 1e-6) / (uni + 1e-6));
        g_inter = 0.0;
        g_desire_sum = 0.0;
        g_count = 0ull;
        __threadfence();
        g_ticket = 0u;
    }
}

extern "C" void kernel_launch(void* const* d_in, const int* in_sizes, int n_in,
                              void* d_out, int out_size) {
    const float4* o1   = (const float4*)d_in[0];
    const float4* o2   = (const float4*)d_in[1];
    const float*  des  = (const float*)d_in[2];
    float*        out  = (float*)d_out;

    const int n_rows = in_sizes[2];   // N = 262144

    // Proven R8 shape: 296 = 148 SMs x 2 blocks, 256 threads, one wave.
    fra_partial_kernel<<<296, 256>>>(o1, o2, (const float4*)des, des, out, n_rows);
}